// round 11
// baseline (speedup 1.0000x reference)
#include <cuda_runtime.h>
#include <cstdint>

#define N_NODES 50000
#define F_IN    256
#define F_OUT   64

// Scratch for projected features XW (12.8 MB) — static device global (no-alloc rule).
__device__ float g_XW[(size_t)N_NODES * F_OUT];

__device__ __forceinline__ uint32_t f2tf32(float x) {
    uint32_t r;
    asm("cvt.rna.tf32.f32 %0, %1;" : "=r"(r) : "f"(x));
    return r;
}

// ---------------------------------------------------------------------------
// Stage 1: XW = X @ W via mma.sync.m16n8k8 tf32.
// Block 128x64, 256 threads (8 warps). B (256x72f) fully resident; A staged in
// 32-wide K chunks, double-buffered (128x36f x2). Smem 108 KB -> 2 CTAs/SM.
// Next chunk's global loads issued into registers before the current chunk's
// MMA burst (latency overlap), STS to the idle buffer, one sync per chunk.
// A_STRIDE=36 (mod32=4): fragment lanes hit banks gid*4+tig -> all 32 distinct.
// B_STRIDE=72 (mod32=8): lanes hit tig*8+gid -> all 32 distinct.
// ---------------------------------------------------------------------------
#define CH 32                      // k per chunk
#define NCH (F_IN / CH)            // 8
#define A_ST 36
#define A_BUF_FLOATS (128 * A_ST)  // 4608
#define B_ST 72
#define SMEM_B_FLOATS (256 * B_ST) // 18432
#define GEMM_SMEM_BYTES ((2 * A_BUF_FLOATS + SMEM_B_FLOATS) * 4)  // 110592 B

__global__ __launch_bounds__(256, 2) void gemm_mma_kernel(const float* __restrict__ X,
                                                          const float* __restrict__ W) {
    extern __shared__ float sm[];
    float* Abuf[2] = { sm, sm + A_BUF_FLOATS };
    float* Bs = sm + 2 * A_BUF_FLOATS;

    const int t = threadIdx.x;
    const int rowBase = blockIdx.x * 128;

    // ---- Fill B: 256 k x 64 n = 4096 float4, 16 per thread (coalesced on n)
#pragma unroll
    for (int i = 0; i < 16; i++) {
        int f  = t + i * 256;
        int k  = f >> 4;
        int n4 = f & 15;
        float4 v = *(const float4*)(W + (size_t)k * F_OUT + n4 * 4);
        uint32_t* dst = (uint32_t*)(Bs + k * B_ST + n4 * 4);
        dst[0] = f2tf32(v.x); dst[1] = f2tf32(v.y);
        dst[2] = f2tf32(v.z); dst[3] = f2tf32(v.w);
    }

    // Per-thread A-chunk mapping: 1024 float4 per chunk, 4 per thread.
    // f = t + i*256 ; m = f>>3 (row), q = f&7 (float4 slot in chunk)
    int aRow[4], aQ[4];
    const float* aSrc[4];
#pragma unroll
    for (int i = 0; i < 4; i++) {
        int f = t + i * 256;
        aRow[i] = f >> 3;
        aQ[i]   = f & 7;
        int gr = rowBase + aRow[i];
        if (gr >= N_NODES) gr = N_NODES - 1;      // clamp; output guarded later
        aSrc[i] = X + (size_t)gr * F_IN + aQ[i] * 4;
    }

    // ---- Preload chunk 0 into buf 0
#pragma unroll
    for (int i = 0; i < 4; i++) {
        float4 v = *(const float4*)(aSrc[i]);
        uint32_t* dst = (uint32_t*)(Abuf[0] + aRow[i] * A_ST + aQ[i] * 4);
        dst[0] = f2tf32(v.x); dst[1] = f2tf32(v.y);
        dst[2] = f2tf32(v.z); dst[3] = f2tf32(v.w);
    }
    __syncthreads();

    const int w    = t >> 5;
    const int lane = t & 31;
    const int gid  = lane >> 2;
    const int tig  = lane & 3;

    float c[8][4];
#pragma unroll
    for (int nt = 0; nt < 8; nt++)
#pragma unroll
        for (int j = 0; j < 4; j++) c[nt][j] = 0.f;

    for (int ch = 0; ch < NCH; ch++) {
        const float* buf = Abuf[ch & 1];

        // Prefetch next chunk into registers (issued before the MMA burst)
        float4 pf[4];
        if (ch + 1 < NCH) {
#pragma unroll
            for (int i = 0; i < 4; i++)
                pf[i] = *(const float4*)(aSrc[i] + (ch + 1) * CH);
        }

        const float* arow0 = buf + (w * 16 + gid) * A_ST;
        const float* arow1 = arow0 + 8 * A_ST;
#pragma unroll
        for (int ks = 0; ks < 4; ks++) {
            const int kc = ks * 8 + tig;
            uint32_t a0 = *(const uint32_t*)(arow0 + kc);
            uint32_t a1 = *(const uint32_t*)(arow1 + kc);
            uint32_t a2 = *(const uint32_t*)(arow0 + kc + 4);
            uint32_t a3 = *(const uint32_t*)(arow1 + kc + 4);

            const float* b_lo = Bs + (size_t)(ch * CH + kc) * B_ST;
            const float* b_hi = b_lo + 4 * B_ST;
#pragma unroll
            for (int nt = 0; nt < 8; nt++) {
                uint32_t b0 = *(const uint32_t*)(b_lo + nt * 8 + gid);
                uint32_t b1 = *(const uint32_t*)(b_hi + nt * 8 + gid);
                asm volatile(
                    "mma.sync.aligned.m16n8k8.row.col.f32.tf32.tf32.f32 "
                    "{%0,%1,%2,%3}, {%4,%5,%6,%7}, {%8,%9}, {%0,%1,%2,%3};"
                    : "+f"(c[nt][0]), "+f"(c[nt][1]), "+f"(c[nt][2]), "+f"(c[nt][3])
                    : "r"(a0), "r"(a1), "r"(a2), "r"(a3), "r"(b0), "r"(b1));
            }
        }

        if (ch + 1 < NCH) {
            float* nb = Abuf[(ch + 1) & 1];
#pragma unroll
            for (int i = 0; i < 4; i++) {
                uint32_t* dst = (uint32_t*)(nb + aRow[i] * A_ST + aQ[i] * 4);
                dst[0] = f2tf32(pf[i].x); dst[1] = f2tf32(pf[i].y);
                dst[2] = f2tf32(pf[i].z); dst[3] = f2tf32(pf[i].w);
            }
        }
        __syncthreads();
    }

    // ---- Epilogue
    const int r0 = rowBase + w * 16 + gid;
    const int r1 = r0 + 8;
#pragma unroll
    for (int nt = 0; nt < 8; nt++) {
        int col = nt * 8 + 2 * tig;
        if (r0 < N_NODES)
            *(float2*)(g_XW + (size_t)r0 * F_OUT + col) = make_float2(c[nt][0], c[nt][1]);
        if (r1 < N_NODES)
            *(float2*)(g_XW + (size_t)r1 * F_OUT + col) = make_float2(c[nt][2], c[nt][3]);
    }
}

// ---------------------------------------------------------------------------
// Stage 2: out[row] += val * XW[col] over E edges.
// 16 threads per 8-edge group: 8 independent LDG.128 gathers in flight
// (MLP=8), then 8 red.global.add.v4.f32.
// ---------------------------------------------------------------------------
__device__ __forceinline__ void red4(float* dst, float s, float4 x) {
    asm volatile("red.global.add.v4.f32 [%0], {%1, %2, %3, %4};"
                 :: "l"(dst), "f"(s * x.x), "f"(s * x.y), "f"(s * x.z), "f"(s * x.w)
                 : "memory");
}

__global__ __launch_bounds__(256) void scatter_kernel(const int*   __restrict__ erow,
                                                      const int*   __restrict__ ecol,
                                                      const float* __restrict__ evals,
                                                      float*       __restrict__ out,
                                                      int E) {
    int idx = blockIdx.x * 256 + threadIdx.x;
    int g = idx >> 4;
    int l = idx & 15;
    int e0 = g * 8;
    if (e0 >= E) return;

    if (e0 + 8 <= E) {
        int4   ra = *(const int4*)(erow + e0);
        int4   rb = *(const int4*)(erow + e0 + 4);
        int4   ca = *(const int4*)(ecol + e0);
        int4   cb = *(const int4*)(ecol + e0 + 4);
        float4 va = *(const float4*)(evals + e0);
        float4 vb = *(const float4*)(evals + e0 + 4);

        // 8 independent gathers in flight
        float4 x0 = ((const float4*)(g_XW + (size_t)ca.x * F_OUT))[l];
        float4 x1 = ((const float4*)(g_XW + (size_t)ca.y * F_OUT))[l];
        float4 x2 = ((const float4*)(g_XW + (size_t)ca.z * F_OUT))[l];
        float4 x3 = ((const float4*)(g_XW + (size_t)ca.w * F_OUT))[l];
        float4 x4 = ((const float4*)(g_XW + (size_t)cb.x * F_OUT))[l];
        float4 x5 = ((const float4*)(g_XW + (size_t)cb.y * F_OUT))[l];
        float4 x6 = ((const float4*)(g_XW + (size_t)cb.z * F_OUT))[l];
        float4 x7 = ((const float4*)(g_XW + (size_t)cb.w * F_OUT))[l];

        red4(out + (size_t)ra.x * F_OUT + l * 4, va.x, x0);
        red4(out + (size_t)ra.y * F_OUT + l * 4, va.y, x1);
        red4(out + (size_t)ra.z * F_OUT + l * 4, va.z, x2);
        red4(out + (size_t)ra.w * F_OUT + l * 4, va.w, x3);
        red4(out + (size_t)rb.x * F_OUT + l * 4, vb.x, x4);
        red4(out + (size_t)rb.y * F_OUT + l * 4, vb.y, x5);
        red4(out + (size_t)rb.z * F_OUT + l * 4, vb.z, x6);
        red4(out + (size_t)rb.w * F_OUT + l * 4, vb.w, x7);
    } else {
        for (int e = e0; e < E; e++) {
            int   r = erow[e], c = ecol[e];
            float v = evals[e];
            float4 x = ((const float4*)(g_XW + (size_t)c * F_OUT))[l];
            red4(out + (size_t)r * F_OUT + l * 4, v, x);
        }
    }
}

// ---------------------------------------------------------------------------
// Launch (graph-capturable: memset node + 2 kernel nodes)
// ---------------------------------------------------------------------------
extern "C" void kernel_launch(void* const* d_in, const int* in_sizes, int n_in,
                              void* d_out, int out_size) {
    const float* X     = (const float*)d_in[0];
    const float* W     = (const float*)d_in[1];
    const int*   erow  = (const int*)d_in[2];
    const int*   ecol  = (const int*)d_in[3];
    const float* evals = (const float*)d_in[4];
    float*       out   = (float*)d_out;
    const int E = in_sizes[2];

    cudaMemsetAsync(d_out, 0, (size_t)out_size * sizeof(float), 0);

    cudaFuncSetAttribute(gemm_mma_kernel, cudaFuncAttributeMaxDynamicSharedMemorySize,
                         GEMM_SMEM_BYTES);
    gemm_mma_kernel<<<(N_NODES + 127) / 128, 256, GEMM_SMEM_BYTES>>>(X, W);

    int groups = (E + 7) / 8;
    long long threads = (long long)groups * 16;
    int blocks = (int)((threads + 255) / 256);
    scatter_kernel<<<blocks, 256>>>(erow, ecol, evals, out, E);
}